// round 1
// baseline (speedup 1.0000x reference)
#include <cuda_runtime.h>

typedef unsigned long long ull;

#define B_   2
#define L_   4096
#define DIN  512
#define H_   8
#define DOUT 512
#define NS   16   // split-K slices for the syrk

// ---------------- scratch (device globals, allocation-free) ----------------
__device__ float g_Gpart[B_][NS][DIN][DIN];   // 32 MB
__device__ float g_G[B_][DIN][DIN];
__device__ float g_T1[B_][DIN][DIN];          // [hk][m]
__device__ float g_KtVp[4][B_*H_][64][64];
__device__ float g_KtV[B_*H_][64][64];
__device__ float g_P[B_][DIN][DIN];           // [j][h*64+v]
__device__ float g_M[B_][DIN][DIN];

// upper-triangle tile list for the 4x4 tile grid of G (128x128 tiles)
__constant__ int c_ti[10] = {0,0,0,0,1,1,1,2,2,3};
__constant__ int c_tj[10] = {0,1,2,3,1,2,3,2,3,3};

// ---------------- f32x2 helpers (packed fp32 FMA, sm_100+) ----------------
__device__ __forceinline__ ull pack2(float x, float y){
    ull r; asm("mov.b64 %0,{%1,%2};" : "=l"(r) : "f"(x), "f"(y)); return r;
}
__device__ __forceinline__ void fma2(ull &d, ull a, ull b){
    asm("fma.rn.f32x2 %0,%1,%2,%0;" : "+l"(d) : "l"(a), "l"(b));
}
__device__ __forceinline__ float2 unpk(ull v){
    float2 r; asm("mov.b64 {%0,%1},%2;" : "=f"(r.x), "=f"(r.y) : "l"(v)); return r;
}

// =====================================================================
// K1: G_b = x_b^T x_b   (split-K over L, symmetric tiles, 128x128, 8x8 micro)
// grid: (10, B_*NS), block 256
// =====================================================================
__global__ __launch_bounds__(256, 2) void k_syrk(const float* __restrict__ x){
    int t  = blockIdx.x;
    int b  = blockIdx.y >> 4;
    int s  = blockIdx.y & 15;
    int p0 = c_ti[t] * 128, q0 = c_tj[t] * 128;
    const float* xb = x + ((size_t)b * L_ + (size_t)s * (L_ / NS)) * DIN;

    __shared__ float As[16][128];
    __shared__ float Bs[16][128];

    ull acc[8][4];
    #pragma unroll
    for (int i = 0; i < 8; i++)
        #pragma unroll
        for (int j = 0; j < 4; j++) acc[i][j] = 0ull;

    int tid = threadIdx.x, tx = tid & 15, ty = tid >> 4;

    for (int l0 = 0; l0 < L_ / NS; l0 += 16) {
        #pragma unroll
        for (int u = 0; u < 2; u++) {
            int i = tid + u * 256;
            int row = i >> 5, c4 = (i & 31) << 2;
            *(float4*)&As[row][c4] = *(const float4*)&xb[(size_t)(l0 + row) * DIN + p0 + c4];
            *(float4*)&Bs[row][c4] = *(const float4*)&xb[(size_t)(l0 + row) * DIN + q0 + c4];
        }
        __syncthreads();
        #pragma unroll
        for (int kk = 0; kk < 16; kk++) {
            float a[8];
            *(float4*)(a)     = *(float4*)&As[kk][ty * 8];
            *(float4*)(a + 4) = *(float4*)&As[kk][ty * 8 + 4];
            ulonglong2 b0 = *(ulonglong2*)&Bs[kk][tx * 8];
            ulonglong2 b1 = *(ulonglong2*)&Bs[kk][tx * 8 + 4];
            ull bv[4] = {b0.x, b0.y, b1.x, b1.y};
            #pragma unroll
            for (int i = 0; i < 8; i++) {
                ull ad = pack2(a[i], a[i]);
                #pragma unroll
                for (int j = 0; j < 4; j++) fma2(acc[i][j], ad, bv[j]);
            }
        }
        __syncthreads();
    }

    float* Cp = &g_Gpart[b][s][0][0];
    #pragma unroll
    for (int i = 0; i < 8; i++) {
        int p = p0 + ty * 8 + i;
        #pragma unroll
        for (int j = 0; j < 4; j++) {
            float2 v = unpk(acc[i][j]);
            int q = q0 + tx * 8 + j * 2;
            *(float2*)&Cp[(size_t)p * DIN + q] = v;
            if (p0 != q0) {               // mirror into lower-triangle tile
                Cp[(size_t)q * DIN + p]       = v.x;
                Cp[(size_t)(q + 1) * DIN + p] = v.y;
            }
        }
    }
}

// reduce split-K partials:  G = sum_s Gpart[s]
__global__ __launch_bounds__(256) void k_reduceG(){
    int t = blockIdx.x * 256 + threadIdx.x;   // 0..131071 (float4 elements)
    int b = t >> 16, e = t & 65535;
    const float4* src = (const float4*)g_Gpart;
    float4 acc = make_float4(0.f, 0.f, 0.f, 0.f);
    #pragma unroll
    for (int s = 0; s < NS; s++) {
        float4 v = src[(size_t)(b * NS + s) * 65536 + e];
        acc.x += v.x; acc.y += v.y; acc.z += v.z; acc.w += v.w;
    }
    ((float4*)g_G)[t] = acc;
}

// =====================================================================
// K2: T1_b[h*64+k, m] = sum_j W_k[h,j,k] * G_b[j,m]   (64x64 tiles)
// grid: (8, 8, B_)  block 256
// =====================================================================
__global__ __launch_bounds__(256) void k_t1(const float* __restrict__ Wk){
    int b  = blockIdx.z;
    int m0 = blockIdx.x * 64, r0 = blockIdx.y * 64;
    int h  = r0 >> 6;
    const float* A  = Wk + (size_t)h * DIN * 64;   // [j][k] 512x64
    const float* Gb = &g_G[b][0][0];

    __shared__ float As[16][64];   // As[jj][k_local]
    __shared__ float Bs[16][64];
    float acc[4][4] = {};
    int tid = threadIdx.x, tx = tid & 15, ty = tid >> 4;

    for (int j0 = 0; j0 < DIN; j0 += 16) {
        int row = tid >> 4, c4 = (tid & 15) << 2;
        *(float4*)&As[row][c4] = *(const float4*)&A[(size_t)(j0 + row) * 64 + c4];
        *(float4*)&Bs[row][c4] = *(const float4*)&Gb[(size_t)(j0 + row) * DIN + m0 + c4];
        __syncthreads();
        #pragma unroll
        for (int kk = 0; kk < 16; kk++) {
            float a[4], bb[4];
            *(float4*)a  = *(float4*)&As[kk][ty * 4];
            *(float4*)bb = *(float4*)&Bs[kk][tx * 4];
            #pragma unroll
            for (int i = 0; i < 4; i++)
                #pragma unroll
                for (int j = 0; j < 4; j++) acc[i][j] = fmaf(a[i], bb[j], acc[i][j]);
        }
        __syncthreads();
    }
    #pragma unroll
    for (int i = 0; i < 4; i++)
        #pragma unroll
        for (int j = 0; j < 4; j++)
            g_T1[b][r0 + ty * 4 + i][m0 + tx * 4 + j] = acc[i][j];
}

// =====================================================================
// K3: KtV[b,h][k,v] = sum_m T1_b[h*64+k, m] * W_v[h,m,v]  (split-K by 4)
// grid: (B_*H_, 4)  block 256
// =====================================================================
__global__ __launch_bounds__(256) void k_ktv(const float* __restrict__ Wv){
    int bh = blockIdx.x, s = blockIdx.y;
    int b = bh >> 3, h = bh & 7;
    const float* A  = &g_T1[b][h * 64][0];           // [k][m] 64 x DIN
    const float* Bv = Wv + (size_t)h * DIN * 64;     // [m][v] 512x64

    __shared__ float As[16][68];   // As[m_local][k]  (transposed load)
    __shared__ float Bs[16][64];
    float acc[4][4] = {};
    int tid = threadIdx.x, tx = tid & 15, ty = tid >> 4;

    for (int m0 = s * 128; m0 < s * 128 + 128; m0 += 16) {
        int row = tid >> 2, c4 = (tid & 3) << 2;     // row = k (0..63), c4 = m offset
        float4 v = *(const float4*)&A[(size_t)row * DIN + m0 + c4];
        As[c4 + 0][row] = v.x; As[c4 + 1][row] = v.y;
        As[c4 + 2][row] = v.z; As[c4 + 3][row] = v.w;
        int r2 = tid >> 4, cc = (tid & 15) << 2;
        *(float4*)&Bs[r2][cc] = *(const float4*)&Bv[(size_t)(m0 + r2) * 64 + cc];
        __syncthreads();
        #pragma unroll
        for (int kk = 0; kk < 16; kk++) {
            float a[4], bb[4];
            *(float4*)a  = *(float4*)&As[kk][ty * 4];
            *(float4*)bb = *(float4*)&Bs[kk][tx * 4];
            #pragma unroll
            for (int i = 0; i < 4; i++)
                #pragma unroll
                for (int j = 0; j < 4; j++) acc[i][j] = fmaf(a[i], bb[j], acc[i][j]);
        }
        __syncthreads();
    }
    #pragma unroll
    for (int i = 0; i < 4; i++)
        #pragma unroll
        for (int j = 0; j < 4; j++)
            g_KtVp[s][bh][ty * 4 + i][tx * 4 + j] = acc[i][j];
}

__global__ __launch_bounds__(256) void k_reduceKtV(){
    int t = blockIdx.x * 256 + threadIdx.x;   // 0..16383 (float4)
    const float4* src = (const float4*)g_KtVp;
    float4 acc = make_float4(0.f, 0.f, 0.f, 0.f);
    #pragma unroll
    for (int s = 0; s < 4; s++) {
        float4 v = src[(size_t)s * 16384 + t];
        acc.x += v.x; acc.y += v.y; acc.z += v.z; acc.w += v.w;
    }
    ((float4*)g_KtV)[t] = acc;
}

// =====================================================================
// K4: P[b][j][h*64+v] = sum_k W_q[h,j,k] * KtV[b,h][k,v]   (K=64)
// grid: (8, B_*H_)  block 256
// =====================================================================
__global__ __launch_bounds__(256) void k_p(const float* __restrict__ Wq){
    int jt = blockIdx.x, bh = blockIdx.y;
    int b = bh >> 3, h = bh & 7;
    int j0 = jt * 64;
    const float* A = Wq + (size_t)h * DIN * 64;   // [j][k]

    __shared__ float As[64][68];   // As[k][j_local]
    __shared__ float Bs[64][64];   // KtV[k][v]
    int tid = threadIdx.x, tx = tid & 15, ty = tid >> 4;

    #pragma unroll
    for (int u = 0; u < 4; u++) {
        int i = tid + u * 256;
        int row = i >> 4, c4 = (i & 15) << 2;     // row = j_local, c4 = k
        float4 v = *(const float4*)&A[(size_t)(j0 + row) * 64 + c4];
        As[c4 + 0][row] = v.x; As[c4 + 1][row] = v.y;
        As[c4 + 2][row] = v.z; As[c4 + 3][row] = v.w;
        ((float4*)Bs)[i] = ((const float4*)&g_KtV[bh][0][0])[i];
    }
    __syncthreads();

    float acc[4][4] = {};
    #pragma unroll 8
    for (int kk = 0; kk < 64; kk++) {
        float a[4], bb[4];
        *(float4*)a  = *(float4*)&As[kk][ty * 4];
        *(float4*)bb = *(float4*)&Bs[kk][tx * 4];
        #pragma unroll
        for (int i = 0; i < 4; i++)
            #pragma unroll
            for (int j = 0; j < 4; j++) acc[i][j] = fmaf(a[i], bb[j], acc[i][j]);
    }
    #pragma unroll
    for (int i = 0; i < 4; i++)
        #pragma unroll
        for (int j = 0; j < 4; j++)
            g_P[b][j0 + ty * 4 + i][h * 64 + tx * 4 + j] = acc[i][j];
}

// =====================================================================
// K5: M_b = P_b (512x512) @ Wo_flat (512x512)    (64x64 tiles)
// grid: (8, 8, B_)  block 256
// =====================================================================
__global__ __launch_bounds__(256) void k_m(const float* __restrict__ Wo){
    int b  = blockIdx.z;
    int o0 = blockIdx.x * 64, j0 = blockIdx.y * 64;
    const float* A = &g_P[b][0][0];               // [j][r]

    __shared__ float As[16][68];   // As[r_local][j_local] (transposed load)
    __shared__ float Bs[16][64];
    float acc[4][4] = {};
    int tid = threadIdx.x, tx = tid & 15, ty = tid >> 4;

    for (int r0 = 0; r0 < DIN; r0 += 16) {
        int row = tid >> 2, c4 = (tid & 3) << 2;  // row = j_local, c4 = r offset
        float4 v = *(const float4*)&A[(size_t)(j0 + row) * DIN + r0 + c4];
        As[c4 + 0][row] = v.x; As[c4 + 1][row] = v.y;
        As[c4 + 2][row] = v.z; As[c4 + 3][row] = v.w;
        int r2 = tid >> 4, cc = (tid & 15) << 2;
        *(float4*)&Bs[r2][cc] = *(const float4*)&Wo[(size_t)(r0 + r2) * DOUT + o0 + cc];
        __syncthreads();
        #pragma unroll
        for (int kk = 0; kk < 16; kk++) {
            float a[4], bb[4];
            *(float4*)a  = *(float4*)&As[kk][ty * 4];
            *(float4*)bb = *(float4*)&Bs[kk][tx * 4];
            #pragma unroll
            for (int i = 0; i < 4; i++)
                #pragma unroll
                for (int j = 0; j < 4; j++) acc[i][j] = fmaf(a[i], bb[j], acc[i][j]);
        }
        __syncthreads();
    }
    #pragma unroll
    for (int i = 0; i < 4; i++)
        #pragma unroll
        for (int j = 0; j < 4; j++)
            g_M[b][j0 + ty * 4 + i][o0 + tx * 4 + j] = acc[i][j];
}

// =====================================================================
// K6: out_b = x_b (4096x512) @ M_b (512x512)   (128x128 tiles, 8x8 micro, f32x2)
// grid: (4, 32, B_)  block 256
// =====================================================================
__global__ __launch_bounds__(256, 2) void k_out(const float* __restrict__ x,
                                                float* __restrict__ out){
    int b  = blockIdx.z;
    int l0 = blockIdx.y * 128, o0 = blockIdx.x * 128;
    const float* xb = x + (size_t)b * L_ * DIN;
    const float* Mb = &g_M[b][0][0];

    __shared__ float As[16][132];  // As[k_local][l_local]  (transposed load, padded)
    __shared__ float Bs[16][128];

    ull acc[8][4];
    #pragma unroll
    for (int i = 0; i < 8; i++)
        #pragma unroll
        for (int j = 0; j < 4; j++) acc[i][j] = 0ull;

    int tid = threadIdx.x, tx = tid & 15, ty = tid >> 4;

    for (int k0 = 0; k0 < DIN; k0 += 16) {
        #pragma unroll
        for (int u = 0; u < 2; u++) {
            int i = tid + u * 256;
            int row = i >> 2, c4 = (i & 3) << 2;        // row = l_local, c4 = k offset
            float4 v = *(const float4*)&xb[(size_t)(l0 + row) * DIN + k0 + c4];
            As[c4 + 0][row] = v.x; As[c4 + 1][row] = v.y;
            As[c4 + 2][row] = v.z; As[c4 + 3][row] = v.w;
            int r2 = i >> 5, cc = (i & 31) << 2;
            *(float4*)&Bs[r2][cc] = *(const float4*)&Mb[(size_t)(k0 + r2) * DOUT + o0 + cc];
        }
        __syncthreads();
        #pragma unroll
        for (int kk = 0; kk < 16; kk++) {
            float a[8];
            *(float4*)(a)     = *(float4*)&As[kk][ty * 8];
            *(float4*)(a + 4) = *(float4*)&As[kk][ty * 8 + 4];
            ulonglong2 b0 = *(ulonglong2*)&Bs[kk][tx * 8];
            ulonglong2 b1 = *(ulonglong2*)&Bs[kk][tx * 8 + 4];
            ull bv[4] = {b0.x, b0.y, b1.x, b1.y};
            #pragma unroll
            for (int i = 0; i < 8; i++) {
                ull ad = pack2(a[i], a[i]);
                #pragma unroll
                for (int j = 0; j < 4; j++) fma2(acc[i][j], ad, bv[j]);
            }
        }
        __syncthreads();
    }

    #pragma unroll
    for (int i = 0; i < 8; i++) {
        int l = l0 + ty * 8 + i;
        float* orow = out + ((size_t)b * L_ + l) * DOUT + o0 + tx * 8;
        #pragma unroll
        for (int j = 0; j < 4; j++) {
            float2 v = unpk(acc[i][j]);
            *(float2*)&orow[j * 2] = v;
        }
    }
}

// =====================================================================
extern "C" void kernel_launch(void* const* d_in, const int* in_sizes, int n_in,
                              void* d_out, int out_size){
    const float* x  = (const float*)d_in[0];
    const float* Wq = (const float*)d_in[1];
    const float* Wk = (const float*)d_in[2];
    const float* Wv = (const float*)d_in[3];
    const float* Wo = (const float*)d_in[4];
    float* out = (float*)d_out;

    k_syrk     <<<dim3(10, B_ * NS), 256>>>(x);
    k_reduceG  <<<512, 256>>>();
    k_t1       <<<dim3(8, 8, B_), 256>>>(Wk);
    k_ktv      <<<dim3(B_ * H_, 4), 256>>>(Wv);
    k_reduceKtV<<<64, 256>>>();
    k_p        <<<dim3(8, B_ * H_), 256>>>(Wq);
    k_m        <<<dim3(8, 8, B_), 256>>>(Wo);
    k_out      <<<dim3(4, 32, B_), 256>>>(x, out);
}

// round 3
// speedup vs baseline: 1.2683x; 1.2683x over previous
#include <cuda_runtime.h>
#include <cuda_bf16.h>
#include <cstdint>

typedef unsigned long long ull;
typedef __nv_bfloat16 bf16;

#define B_   2
#define L_   4096
#define DIN  512
#define H_   8

#define BM 128
#define BN 128
#define BK 32
#define APAD 40                    // padded K stride (elements): 80 bytes/row
#define STG_ELEMS (BM * APAD)      // 5120 bf16 = 10240 bytes per matrix per stage

// ---------------- scratch (device globals, allocation-free) ----------------
__device__ __align__(256) bf16 g_xtHi[B_][DIN][L_];   // x^T hi  [p][l]
__device__ __align__(256) bf16 g_xtLo[B_][DIN][L_];
__device__ __align__(256) bf16 g_xHi [B_][L_][DIN];   // x hi    [l][p]
__device__ __align__(256) bf16 g_xLo [B_][L_][DIN];
__device__ __align__(256) float g_Gp3[B_*3][DIN][DIN];
__device__ __align__(256) float g_G  [B_][DIN][DIN];
__device__ __align__(256) float g_T1 [B_][DIN][DIN];
__device__ __align__(256) float g_KtVp[4][B_*H_][64][64];
__device__ __align__(256) float g_P  [B_][DIN][DIN];
__device__ __align__(256) bf16 g_MtHi[B_][DIN][DIN];  // M^T hi  [o][j]
__device__ __align__(256) bf16 g_MtLo[B_][DIN][DIN];

// ---------------- PTX helpers ----------------
__device__ __forceinline__ uint32_t smem_u32(const void* p){
    uint32_t a;
    asm("{ .reg .u64 t; cvta.to.shared.u64 t, %1; cvt.u32.u64 %0, t; }" : "=r"(a) : "l"(p));
    return a;
}
__device__ __forceinline__ void cp16(uint32_t sa, const void* ga){
    asm volatile("cp.async.cg.shared.global [%0], [%1], 16;" :: "r"(sa), "l"(ga));
}
#define CP_COMMIT() asm volatile("cp.async.commit_group;" ::: "memory")

__device__ __forceinline__ void ldmx4(uint32_t r[4], uint32_t addr){
    asm volatile("ldmatrix.sync.aligned.m8n8.x4.shared.b16 {%0,%1,%2,%3}, [%4];"
        : "=r"(r[0]), "=r"(r[1]), "=r"(r[2]), "=r"(r[3]) : "r"(addr));
}
__device__ __forceinline__ void mma16816(float c[4], const uint32_t a[4],
                                         uint32_t b0, uint32_t b1){
    asm volatile("mma.sync.aligned.m16n8k16.row.col.f32.bf16.bf16.f32 "
        "{%0,%1,%2,%3}, {%4,%5,%6,%7}, {%8,%9}, {%0,%1,%2,%3};"
        : "+f"(c[0]), "+f"(c[1]), "+f"(c[2]), "+f"(c[3])
        : "r"(a[0]), "r"(a[1]), "r"(a[2]), "r"(a[3]), "r"(b0), "r"(b1));
}

// =====================================================================
// split + transpose: x -> (xHi,xLo) row-major, (xtHi,xtLo) transposed
// =====================================================================
__global__ __launch_bounds__(256) void k_split(const float* __restrict__ x){
    __shared__ float s[32][33];
    int p0 = blockIdx.x * 32, l0 = blockIdx.y * 32, b = blockIdx.z;
    int tx = threadIdx.x & 31, ty = threadIdx.x >> 5;
    const float* xb = x + ((size_t)b * L_ + l0) * DIN + p0;
    #pragma unroll
    for (int u = 0; u < 4; u++) {
        int lr = ty + u * 8;
        s[lr][tx] = xb[(size_t)lr * DIN + tx];
    }
    __syncthreads();
    #pragma unroll
    for (int u = 0; u < 4; u++) {
        int lr = ty + u * 8;
        float v = s[lr][tx];
        bf16 h = __float2bfloat16(v);
        bf16 lo = __float2bfloat16(v - __bfloat162float(h));
        g_xHi[b][l0 + lr][p0 + tx] = h;
        g_xLo[b][l0 + lr][p0 + tx] = lo;
        int pr = ty + u * 8;
        float w = s[tx][pr];
        bf16 ht = __float2bfloat16(w);
        bf16 lt = __float2bfloat16(w - __bfloat162float(ht));
        g_xtHi[b][p0 + pr][l0 + tx] = ht;
        g_xtLo[b][p0 + pr][l0 + tx] = lt;
    }
}

// =====================================================================
// mma.sync bf16 GEMM engine: 128x128x32 tile, double-buffered cp.async.
// A row-major [M][K], B = B^T row-major [N][K]. Accum fp32 in registers.
// =====================================================================
struct GemmArgs {
    const bf16* Ap[3];
    const bf16* Bp[3];
    int lda, ldb;
    int cshift;     // log2(chunks per product)
    int nt;         // total K chunks
};

__device__ __forceinline__ void gemm_body(uint32_t sA, uint32_t sB,
                                          const GemmArgs& g, int m0, int n0,
                                          float acc[4][4][4])
{
    int tid = threadIdx.x, lane = tid & 31, wid = tid >> 5;
    int mw = wid & 1, nw = wid >> 1;

    auto load = [&](int j){
        int prod = j >> g.cshift;
        const bf16* Ac = g.Ap[prod];
        const bf16* Bc = g.Bp[prod];
        int kb = (j - (prod << g.cshift)) * BK;
        uint32_t sa = sA + (j & 1) * 10240;
        uint32_t sb = sB + (j & 1) * 10240;
        #pragma unroll
        for (int u = 0; u < 2; u++) {
            int idx = tid + u * 256;
            int r = idx >> 2, c = idx & 3;
            cp16(sa + r * 80 + c * 16, Ac + (size_t)(m0 + r) * g.lda + kb + c * 8);
            cp16(sb + r * 80 + c * 16, Bc + (size_t)(n0 + r) * g.ldb + kb + c * 8);
        }
    };

    load(0); CP_COMMIT();

    for (int i = 0; i < g.nt; i++) {
        if (i + 1 < g.nt) {
            load(i + 1); CP_COMMIT();
            asm volatile("cp.async.wait_group 1;" ::: "memory");
        } else {
            asm volatile("cp.async.wait_group 0;" ::: "memory");
        }
        __syncthreads();

        uint32_t sa = sA + (i & 1) * 10240;
        uint32_t sb = sB + (i & 1) * 10240;
        #pragma unroll
        for (int ks = 0; ks < BK; ks += 16) {
            uint32_t a[4][4], b[2][4];
            #pragma unroll
            for (int mi = 0; mi < 4; mi++) {
                int row = mw * 64 + mi * 16 + (lane & 15);
                int col = ks + (lane >> 4) * 8;
                ldmx4(a[mi], sa + row * 80 + col * 2);
            }
            #pragma unroll
            for (int bi = 0; bi < 2; bi++) {
                int row = nw * 32 + bi * 16 + ((lane >> 4) << 3) + (lane & 7);
                int col = ks + ((lane >> 3) & 1) * 8;
                ldmx4(b[bi], sb + row * 80 + col * 2);
            }
            #pragma unroll
            for (int mi = 0; mi < 4; mi++)
                #pragma unroll
                for (int ni = 0; ni < 4; ni++)
                    mma16816(acc[mi][ni], a[mi], b[ni >> 1][(ni & 1) * 2],
                             b[ni >> 1][(ni & 1) * 2 + 1]);
        }
        __syncthreads();
    }
}

__device__ __forceinline__ void epi_store(float acc[4][4][4], float* C, int ldc,
                                          int m0, int n0){
    int lane = threadIdx.x & 31, wid = threadIdx.x >> 5;
    int mw = wid & 1, nw = wid >> 1;
    int rbase = m0 + mw * 64 + (lane >> 2);
    int cbase = n0 + nw * 32 + (lane & 3) * 2;
    #pragma unroll
    for (int mi = 0; mi < 4; mi++) {
        #pragma unroll
        for (int ni = 0; ni < 4; ni++) {
            int r = rbase + mi * 16;
            int c = cbase + ni * 8;
            *(float2*)&C[(size_t)r * ldc + c] = make_float2(acc[mi][ni][0], acc[mi][ni][1]);
            *(float2*)&C[(size_t)(r + 8) * ldc + c] = make_float2(acc[mi][ni][2], acc[mi][ni][3]);
        }
    }
}

// G split products: z = b*3 + prod; C = A . B^T over K = 4096
__global__ __launch_bounds__(256) void k_gemm_g(){
    __shared__ __align__(16) bf16 sAm[2][BM][APAD];
    __shared__ __align__(16) bf16 sBm[2][BN][APAD];
    int n0 = blockIdx.x * 128, m0 = blockIdx.y * 128;
    int z = blockIdx.z, b = z / 3, prod = z - b * 3;

    GemmArgs g;
    g.Ap[0] = g.Ap[1] = g.Ap[2] = (prod == 2) ? &g_xtLo[b][0][0] : &g_xtHi[b][0][0];
    g.Bp[0] = g.Bp[1] = g.Bp[2] = (prod == 1) ? &g_xtLo[b][0][0] : &g_xtHi[b][0][0];
    g.lda = L_; g.ldb = L_; g.cshift = 7; g.nt = 128;

    float acc[4][4][4] = {};
    gemm_body(smem_u32(&sAm[0][0][0]), smem_u32(&sBm[0][0][0]), g, m0, n0, acc);
    epi_store(acc, &g_Gp3[z][0][0], DIN, m0, n0);
}

__global__ __launch_bounds__(256) void k_reduceG3(){
    int t = blockIdx.x * 256 + threadIdx.x;
    int b = t >> 16, e = t & 65535;
    const float4* p0 = (const float4*)&g_Gp3[b * 3 + 0][0][0];
    const float4* p1 = (const float4*)&g_Gp3[b * 3 + 1][0][0];
    const float4* p2 = (const float4*)&g_Gp3[b * 3 + 2][0][0];
    float4 a = p0[e], c = p1[e], d = p2[e];
    ((float4*)&g_G[b][0][0])[e] = make_float4(a.x + c.x + d.x, a.y + c.y + d.y,
                                              a.z + c.z + d.z, a.w + c.w + d.w);
}

// out = x . M: 3 split products accumulated in registers, K = 3*512
__global__ __launch_bounds__(256) void k_gemm_out(float* __restrict__ out){
    __shared__ __align__(16) bf16 sAm[2][BM][APAD];
    __shared__ __align__(16) bf16 sBm[2][BN][APAD];
    int n0 = blockIdx.x * 128, m0 = blockIdx.y * 128, b = blockIdx.z;

    GemmArgs g;
    g.Ap[0] = &g_xHi[b][0][0]; g.Ap[1] = &g_xHi[b][0][0]; g.Ap[2] = &g_xLo[b][0][0];
    g.Bp[0] = &g_MtHi[b][0][0]; g.Bp[1] = &g_MtLo[b][0][0]; g.Bp[2] = &g_MtHi[b][0][0];
    g.lda = DIN; g.ldb = DIN; g.cshift = 4; g.nt = 48;

    float acc[4][4][4] = {};
    gemm_body(smem_u32(&sAm[0][0][0]), smem_u32(&sBm[0][0][0]), g, m0, n0, acc);
    epi_store(acc, out + (size_t)b * L_ * DIN, DIN, m0, n0);
}

// =====================================================================
// glue (fp32 SIMT, exact)
// =====================================================================
__global__ __launch_bounds__(256) void k_t1(const float* __restrict__ Wk){
    int b  = blockIdx.z;
    int m0 = blockIdx.x * 64, r0 = blockIdx.y * 64;
    int h  = r0 >> 6;
    const float* A  = Wk + (size_t)h * DIN * 64;
    const float* Gb = &g_G[b][0][0];
    __shared__ float As[16][64];
    __shared__ float Bs[16][64];
    float acc[4][4] = {};
    int tid = threadIdx.x, tx = tid & 15, ty = tid >> 4;
    for (int j0 = 0; j0 < DIN; j0 += 16) {
        int row = tid >> 4, c4 = (tid & 15) << 2;
        *(float4*)&As[row][c4] = *(const float4*)&A[(size_t)(j0 + row) * 64 + c4];
        *(float4*)&Bs[row][c4] = *(const float4*)&Gb[(size_t)(j0 + row) * DIN + m0 + c4];
        __syncthreads();
        #pragma unroll
        for (int kk = 0; kk < 16; kk++) {
            float a[4], bb[4];
            *(float4*)a  = *(float4*)&As[kk][ty * 4];
            *(float4*)bb = *(float4*)&Bs[kk][tx * 4];
            #pragma unroll
            for (int i = 0; i < 4; i++)
                #pragma unroll
                for (int j = 0; j < 4; j++) acc[i][j] = fmaf(a[i], bb[j], acc[i][j]);
        }
        __syncthreads();
    }
    #pragma unroll
    for (int i = 0; i < 4; i++)
        #pragma unroll
        for (int j = 0; j < 4; j++)
            g_T1[b][r0 + ty * 4 + i][m0 + tx * 4 + j] = acc[i][j];
}

__global__ __launch_bounds__(256) void k_ktv(const float* __restrict__ Wv){
    int bh = blockIdx.x, s = blockIdx.y;
    int b = bh >> 3, h = bh & 7;
    const float* A  = &g_T1[b][h * 64][0];
    const float* Bv = Wv + (size_t)h * DIN * 64;
    __shared__ float As[16][68];
    __shared__ float Bs[16][64];
    float acc[4][4] = {};
    int tid = threadIdx.x, tx = tid & 15, ty = tid >> 4;
    for (int m0 = s * 128; m0 < s * 128 + 128; m0 += 16) {
        int row = tid >> 2, c4 = (tid & 3) << 2;
        float4 v = *(const float4*)&A[(size_t)row * DIN + m0 + c4];
        As[c4 + 0][row] = v.x; As[c4 + 1][row] = v.y;
        As[c4 + 2][row] = v.z; As[c4 + 3][row] = v.w;
        int r2 = tid >> 4, cc = (tid & 15) << 2;
        *(float4*)&Bs[r2][cc] = *(const float4*)&Bv[(size_t)(m0 + r2) * 64 + cc];
        __syncthreads();
        #pragma unroll
        for (int kk = 0; kk < 16; kk++) {
            float a[4], bb[4];
            *(float4*)a  = *(float4*)&As[kk][ty * 4];
            *(float4*)bb = *(float4*)&Bs[kk][tx * 4];
            #pragma unroll
            for (int i = 0; i < 4; i++)
                #pragma unroll
                for (int j = 0; j < 4; j++) acc[i][j] = fmaf(a[i], bb[j], acc[i][j]);
        }
        __syncthreads();
    }
    #pragma unroll
    for (int i = 0; i < 4; i++)
        #pragma unroll
        for (int j = 0; j < 4; j++)
            g_KtVp[s][bh][ty * 4 + i][tx * 4 + j] = acc[i][j];
}

__global__ __launch_bounds__(256) void k_p(const float* __restrict__ Wq){
    int jt = blockIdx.x, bh = blockIdx.y;
    int b = bh >> 3, h = bh & 7;
    int j0 = jt * 64;
    const float* A = Wq + (size_t)h * DIN * 64;
    __shared__ float As[64][68];
    __shared__ float Bs[64][64];
    int tid = threadIdx.x, tx = tid & 15, ty = tid >> 4;
    const float4* s0 = (const float4*)&g_KtVp[0][bh][0][0];
    const float4* s1 = (const float4*)&g_KtVp[1][bh][0][0];
    const float4* s2 = (const float4*)&g_KtVp[2][bh][0][0];
    const float4* s3 = (const float4*)&g_KtVp[3][bh][0][0];
    #pragma unroll
    for (int u = 0; u < 4; u++) {
        int i = tid + u * 256;
        int row = i >> 4, c4 = (i & 15) << 2;
        float4 v = *(const float4*)&A[(size_t)(j0 + row) * 64 + c4];
        As[c4 + 0][row] = v.x; As[c4 + 1][row] = v.y;
        As[c4 + 2][row] = v.z; As[c4 + 3][row] = v.w;
        float4 a = s0[i], bb = s1[i], c = s2[i], d = s3[i];
        ((float4*)Bs)[i] = make_float4(a.x + bb.x + c.x + d.x, a.y + bb.y + c.y + d.y,
                                       a.z + bb.z + c.z + d.z, a.w + bb.w + c.w + d.w);
    }
    __syncthreads();
    float acc[4][4] = {};
    #pragma unroll 8
    for (int kk = 0; kk < 64; kk++) {
        float a[4], bb[4];
        *(float4*)a  = *(float4*)&As[kk][ty * 4];
        *(float4*)bb = *(float4*)&Bs[kk][tx * 4];
        #pragma unroll
        for (int i = 0; i < 4; i++)
            #pragma unroll
            for (int j = 0; j < 4; j++) acc[i][j] = fmaf(a[i], bb[j], acc[i][j]);
    }
    #pragma unroll
    for (int i = 0; i < 4; i++)
        #pragma unroll
        for (int j = 0; j < 4; j++)
            g_P[b][j0 + ty * 4 + i][h * 64 + tx * 4 + j] = acc[i][j];
}

// M = P . Wo  -> write transposed bf16 hi/lo
__global__ __launch_bounds__(256) void k_m(const float* __restrict__ Wo){
    int b  = blockIdx.z;
    int o0 = blockIdx.x * 64, j0 = blockIdx.y * 64;
    const float* A = &g_P[b][0][0];
    __shared__ float As[16][68];
    __shared__ float Bs[16][64];
    float acc[4][4] = {};
    int tid = threadIdx.x, tx = tid & 15, ty = tid >> 4;
    for (int r0 = 0; r0 < DIN; r0 += 16) {
        int row = tid >> 2, c4 = (tid & 3) << 2;
        float4 v = *(const float4*)&A[(size_t)(j0 + row) * DIN + r0 + c4];
        As[c4 + 0][row] = v.x; As[c4 + 1][row] = v.y;
        As[c4 + 2][row] = v.z; As[c4 + 3][row] = v.w;
        int r2 = tid >> 4, cc = (tid & 15) << 2;
        *(float4*)&Bs[r2][cc] = *(const float4*)&Wo[(size_t)(r0 + r2) * DIN + o0 + cc];
        __syncthreads();
        #pragma unroll
        for (int kk = 0; kk < 16; kk++) {
            float a[4], bb[4];
            *(float4*)a  = *(float4*)&As[kk][ty * 4];
            *(float4*)bb = *(float4*)&Bs[kk][tx * 4];
            #pragma unroll
            for (int i = 0; i < 4; i++)
                #pragma unroll
                for (int j = 0; j < 4; j++) acc[i][j] = fmaf(a[i], bb[j], acc[i][j]);
        }
        __syncthreads();
    }
    #pragma unroll
    for (int i = 0; i < 4; i++) {
        int jj = j0 + ty * 4 + i;
        #pragma unroll
        for (int j = 0; j < 4; j++) {
            int oo = o0 + tx * 4 + j;
            float v = acc[i][j];
            bf16 h = __float2bfloat16(v);
            bf16 lo = __float2bfloat16(v - __bfloat162float(h));
            g_MtHi[b][oo][jj] = h;
            g_MtLo[b][oo][jj] = lo;
        }
    }
}

// =====================================================================
extern "C" void kernel_launch(void* const* d_in, const int* in_sizes, int n_in,
                              void* d_out, int out_size){
    const float* x  = (const float*)d_in[0];
    const float* Wq = (const float*)d_in[1];
    const float* Wk = (const float*)d_in[2];
    const float* Wv = (const float*)d_in[3];
    const float* Wo = (const float*)d_in[4];
    float* out = (float*)d_out;

    k_split   <<<dim3(DIN / 32, L_ / 32, B_), 256>>>(x);
    k_gemm_g  <<<dim3(4, 4, B_ * 3), 256>>>();
    k_reduceG3<<<512, 256>>>();
    k_t1      <<<dim3(8, 8, B_), 256>>>(Wk);
    k_ktv     <<<dim3(B_ * H_, 4), 256>>>(Wv);
    k_p       <<<dim3(8, B_ * H_), 256>>>(Wq);
    k_m       <<<dim3(8, 8, B_), 256>>>(Wo);
    k_gemm_out<<<dim3(4, 32, B_), 256>>>(out);
}